// round 4
// baseline (speedup 1.0000x reference)
#include <cuda_runtime.h>
#include <cuda_bf16.h>
#include <cstdint>

#define NROWS 8192
#define SEQLEN 512
#define DIMK 256
static constexpr float INV_TEMP = 1.0f / 0.07f;

__device__ __nv_bfloat16 g_nb[NROWS * DIMK];   // normalized bf16 (MMA input)
__device__ float         g_nf[NROWS * DIMK];   // normalized fp32 (pos kernel)
__device__ float         g_partial[2][NROWS];  // per-chunk diag-excluded exp rowsums
__device__ float         g_pos[NROWS];

// ---------------- helpers ----------------
static __device__ __forceinline__ uint32_t smem_u32(const void* p) {
    uint32_t a;
    asm("{ .reg .u64 t; cvta.to.shared.u64 t, %1; cvt.u32.u64 %0, t; }" : "=r"(a) : "l"(p));
    return a;
}
static __device__ __forceinline__ void cp_async16(uint32_t saddr, const void* gptr) {
    asm volatile("cp.async.cg.shared.global [%0], [%1], 16;" :: "r"(saddr), "l"(gptr) : "memory");
}
static __device__ __forceinline__ void cp_commit() {
    asm volatile("cp.async.commit_group;" ::: "memory");
}
template <int N>
static __device__ __forceinline__ void cp_wait() {
    asm volatile("cp.async.wait_group %0;" :: "n"(N) : "memory");
}
static __device__ __forceinline__ void ldsm_x4(uint32_t& r0, uint32_t& r1, uint32_t& r2, uint32_t& r3, uint32_t a) {
    asm volatile("ldmatrix.sync.aligned.m8n8.x4.shared.b16 {%0,%1,%2,%3}, [%4];"
                 : "=r"(r0), "=r"(r1), "=r"(r2), "=r"(r3) : "r"(a));
}
static __device__ __forceinline__ void mma16816(float* c, const uint32_t* a, uint32_t b0, uint32_t b1) {
    asm volatile("mma.sync.aligned.m16n8k16.row.col.f32.bf16.bf16.f32 "
                 "{%0,%1,%2,%3}, {%4,%5,%6,%7}, {%8,%9}, {%0,%1,%2,%3};"
                 : "+f"(c[0]), "+f"(c[1]), "+f"(c[2]), "+f"(c[3])
                 : "r"(a[0]), "r"(a[1]), "r"(a[2]), "r"(a[3]), "r"(b0), "r"(b1));
}

// ---------------- GEMM config ----------------
static constexpr int TILE_M = 128, TILE_N = 128, TILES_PER_CTA = 32, NCHUNK = 2;
static constexpr int TILE_BYTES = TILE_M * DIMK * 2;           // 65536 (512B per row)
static constexpr int SM_A = 0, SM_B0 = TILE_BYTES, SM_B1 = 2 * TILE_BYTES;
static constexpr int SMEM_TOTAL = 3 * TILE_BYTES;              // 196608

// Async-load one [128 x 512B] tile. 16B units; unit u of row r goes to
// swizzled offset r*512 + ((u ^ (r&7))<<4)  (conflict-free for ldmatrix).
static __device__ __forceinline__ void load_tile_async(uint32_t dst, const __nv_bfloat16* __restrict__ src, int tid) {
#pragma unroll
    for (int i = 0; i < 16; i++) {
        int idx = tid + i * 256;
        int row = idx >> 5, u = idx & 31;
        uint32_t so = dst + (uint32_t)(row << 9) + (uint32_t)(((u ^ (row & 7)) << 4));
        cp_async16(so, src + (size_t)row * DIMK + u * 8);
    }
}

// ---------------- Kernel 1: L2 normalize ----------------
__global__ void __launch_bounds__(256) normalize_k(const float* __restrict__ emb, float* out) {
    if (blockIdx.x == 0 && threadIdx.x == 0) *out = 0.0f;
    const int wid = threadIdx.x >> 5, lid = threadIdx.x & 31;
    const int row = blockIdx.x * 8 + wid;
    const float4* src = reinterpret_cast<const float4*>(emb + (size_t)row * DIMK);
    float4 a = src[lid * 2], b = src[lid * 2 + 1];
    float ss = a.x*a.x + a.y*a.y + a.z*a.z + a.w*a.w + b.x*b.x + b.y*b.y + b.z*b.z + b.w*b.w;
#pragma unroll
    for (int o = 16; o > 0; o >>= 1) ss += __shfl_xor_sync(0xffffffffu, ss, o);
    const float inv = 1.0f / fmaxf(sqrtf(ss), 1e-12f);
    a.x *= inv; a.y *= inv; a.z *= inv; a.w *= inv;
    b.x *= inv; b.y *= inv; b.z *= inv; b.w *= inv;
    reinterpret_cast<float4*>(g_nf + (size_t)row * DIMK)[lid * 2]     = a;
    reinterpret_cast<float4*>(g_nf + (size_t)row * DIMK)[lid * 2 + 1] = b;
    uint4 pk;
    pk.x = ((uint32_t)__bfloat16_as_ushort(__float2bfloat16_rn(a.y)) << 16) | (uint32_t)__bfloat16_as_ushort(__float2bfloat16_rn(a.x));
    pk.y = ((uint32_t)__bfloat16_as_ushort(__float2bfloat16_rn(a.w)) << 16) | (uint32_t)__bfloat16_as_ushort(__float2bfloat16_rn(a.z));
    pk.z = ((uint32_t)__bfloat16_as_ushort(__float2bfloat16_rn(b.y)) << 16) | (uint32_t)__bfloat16_as_ushort(__float2bfloat16_rn(b.x));
    pk.w = ((uint32_t)__bfloat16_as_ushort(__float2bfloat16_rn(b.w)) << 16) | (uint32_t)__bfloat16_as_ushort(__float2bfloat16_rn(b.z));
    reinterpret_cast<uint4*>(g_nb + (size_t)row * DIMK)[lid] = pk;
}

// ---------------- Kernel 2: positive sums (exact fp32) ----------------
__global__ void __launch_bounds__(256) pos_k() {
    const int wid = threadIdx.x >> 5, lid = threadIdx.x & 31;
    const int row = blockIdx.x * 8 + wid;
    const float4* xi = reinterpret_cast<const float4*>(g_nf + (size_t)row * DIMK);
    const float4 a = xi[lid * 2], b = xi[lid * 2 + 1];
    const int p = row & (SEQLEN - 1);
    float ps = 1e-8f;
#pragma unroll
    for (int dd = -5; dd <= 5; dd++) {
        if (dd == 0) continue;
        int pj = p + dd;
        if (pj < 0 || pj >= SEQLEN) continue;
        const float4* xj = reinterpret_cast<const float4*>(g_nf + (size_t)(row + dd) * DIMK);
        float4 c = xj[lid * 2], e = xj[lid * 2 + 1];
        float dt = a.x*c.x + a.y*c.y + a.z*c.z + a.w*c.w + b.x*e.x + b.y*e.y + b.z*e.z + b.w*e.w;
#pragma unroll
        for (int o = 16; o > 0; o >>= 1) dt += __shfl_xor_sync(0xffffffffu, dt, o);
        ps += __expf(dt * INV_TEMP);
    }
    if (lid == 0) g_pos[row] = ps;
}

// ---------------- Kernel 3: mma.sync GEMM + fused exp rowsum ----------------
// 8 warps: wr = wid&3 (M quarter, 32 rows), wc = wid>>2 (N half, 64 cols).
// Per warp: 2 m16 tiles x 8 n8 tiles, K=256 in 16 k16 steps.
__global__ void __launch_bounds__(256, 1) contrast_gemm() {
    extern __shared__ char smem[];
    const int tid = threadIdx.x, lane = tid & 31, wid = tid >> 5;
    const int wr = wid & 3, wc = wid >> 2;
    const uint32_t sb = smem_u32(smem);
    const int rowblk = blockIdx.x;          // 0..63
    const int chunk  = blockIdx.y;          // 0..1
    const int col0 = chunk * (TILES_PER_CTA * TILE_N);

    // Prologue: A + B0 (group 0), B1 (group 1)
    load_tile_async(sb + SM_A,  g_nb + (size_t)(rowblk * TILE_M) * DIMK, tid);
    load_tile_async(sb + SM_B0, g_nb + (size_t)col0 * DIMK, tid);
    cp_commit();
    load_tile_async(sb + SM_B1, g_nb + (size_t)(col0 + TILE_N) * DIMK, tid);
    cp_commit();

    // ldmatrix lane addressing (x4, non-trans, both operands K-contiguous):
    // lanes 0-7 -> rows 0-7 (k lo), 8-15 -> rows 8-15 (k lo),
    // 16-23 -> rows 0-7 (k hi), 24-31 -> rows 8-15 (k hi)
    const int lr = lane & 15;          // row within 16
    const int hi = lane >> 4;          // k-half select
    const uint32_t rx = (uint32_t)(lr & 7);
    uint32_t a_base[2], b_roff[4];
#pragma unroll
    for (int mt = 0; mt < 2; mt++)
        a_base[mt] = sb + SM_A + (uint32_t)((wr * 32 + mt * 16 + lr) << 9);
#pragma unroll
    for (int np = 0; np < 4; np++)
        b_roff[np] = (uint32_t)((wc * 64 + np * 16 + lr) << 9);

    float rs[4] = {0.f, 0.f, 0.f, 0.f};   // rowsums: [mt*2 + rowhalf]
    const int myrow_base = rowblk * TILE_M + wr * 32 + (lane >> 2);

    for (int t = 0; t < TILES_PER_CTA; t++) {
        cp_wait<1>();                       // B[t] (and A) resident
        __syncthreads();

        const uint32_t bbase = sb + ((t & 1) ? SM_B1 : SM_B0);
        float acc[2][8][4];
#pragma unroll
        for (int mt = 0; mt < 2; mt++)
#pragma unroll
            for (int nt = 0; nt < 8; nt++)
#pragma unroll
                for (int j = 0; j < 4; j++) acc[mt][nt][j] = 0.f;

#pragma unroll 4
        for (int ks = 0; ks < 16; ks++) {
            const uint32_t koff = (uint32_t)(((2 * ks + hi) ^ rx) << 4);
            uint32_t a[2][4];
            ldsm_x4(a[0][0], a[0][1], a[0][2], a[0][3], a_base[0] + koff);
            ldsm_x4(a[1][0], a[1][1], a[1][2], a[1][3], a_base[1] + koff);
#pragma unroll
            for (int np = 0; np < 4; np++) {
                uint32_t b0, b1, b2, b3;   // b0/b2: n-tile 2np, b1/b3: n-tile 2np+1
                ldsm_x4(b0, b1, b2, b3, bbase + b_roff[np] + koff);
#pragma unroll
                for (int mt = 0; mt < 2; mt++) {
                    mma16816(acc[mt][np * 2 + 0], a[mt], b0, b2);
                    mma16816(acc[mt][np * 2 + 1], a[mt], b1, b3);
                }
            }
        }
        __syncthreads();                    // all reads of buf[t&1] done

        if (t + 2 < TILES_PER_CTA)
            load_tile_async(sb + ((t & 1) ? SM_B1 : SM_B0),
                            g_nb + (size_t)(col0 + (t + 2) * TILE_N) * DIMK, tid);
        cp_commit();

        // Fused epilogue: exp + diag-excluded rowsum (registers only)
        const int colbase = col0 + t * TILE_N + wc * 64 + (lane & 3) * 2;
        const bool hasdiag = (col0 + t * TILE_N) == rowblk * TILE_M;
#pragma unroll
        for (int mt = 0; mt < 2; mt++)
#pragma unroll
            for (int nt = 0; nt < 8; nt++) {
                const int c01 = colbase + nt * 8;
#pragma unroll
                for (int j = 0; j < 4; j++) {
                    float e = __expf(acc[mt][nt][j] * INV_TEMP);
                    if (hasdiag) {
                        const int col = c01 + (j & 1);
                        const int row = myrow_base + mt * 16 + (j >> 1) * 8;
                        e = (col != row) ? e : 0.0f;
                    }
                    rs[mt * 2 + (j >> 1)] += e;
                }
            }
    }

    // Reduce rowsums: lanes sharing lane>>2 hold the same rows
#pragma unroll
    for (int q = 0; q < 4; q++) {
        rs[q] += __shfl_xor_sync(0xffffffffu, rs[q], 1);
        rs[q] += __shfl_xor_sync(0xffffffffu, rs[q], 2);
    }
    float* red = reinterpret_cast<float*>(smem);   // 2*128 floats, reuse SMEM
    __syncthreads();
    if ((lane & 3) == 0) {
#pragma unroll
        for (int q = 0; q < 4; q++) {
            const int rl = wr * 32 + (q >> 1) * 16 + (q & 1) * 8 + (lane >> 2);
            red[wc * 128 + rl] = rs[q];
        }
    }
    __syncthreads();
    if (tid < 128)
        g_partial[chunk][rowblk * TILE_M + tid] = red[tid] + red[128 + tid];
}

// ---------------- Kernel 4: finalize ----------------
__global__ void __launch_bounds__(256) finalize_k(float* out) {
    const int row = blockIdx.x * 256 + threadIdx.x;
    const float all = 1e-8f + g_partial[0][row] + g_partial[1][row];
    float l = __logf(g_pos[row] / all);
#pragma unroll
    for (int o = 16; o > 0; o >>= 1) l += __shfl_xor_sync(0xffffffffu, l, o);
    __shared__ float s[8];
    if ((threadIdx.x & 31) == 0) s[threadIdx.x >> 5] = l;
    __syncthreads();
    if (threadIdx.x == 0) {
        float t = 0.0f;
#pragma unroll
        for (int i = 0; i < 8; i++) t += s[i];
        atomicAdd(out, -t * (1.0f / (float)NROWS));
    }
}

extern "C" void kernel_launch(void* const* d_in, const int* in_sizes, int n_in,
                              void* d_out, int out_size) {
    const float* emb = (const float*)d_in[0];
    float* out = (float*)d_out;
    cudaFuncSetAttribute(contrast_gemm, cudaFuncAttributeMaxDynamicSharedMemorySize, SMEM_TOTAL);
    normalize_k<<<NROWS / 8, 256>>>(emb, out);
    pos_k<<<NROWS / 8, 256>>>();
    contrast_gemm<<<dim3(64, NCHUNK), 256, SMEM_TOTAL>>>();
    finalize_k<<<NROWS / 256, 256>>>(out);
}

// round 6
// speedup vs baseline: 1.0321x; 1.0321x over previous
#include <cuda_runtime.h>
#include <cuda_bf16.h>
#include <cstdint>

#define NROWS 8192
#define SEQLEN 512
#define DIMK 256
#define NBLK 64                 // 8192 / 128 row-blocks
#define NTILES_TRI 2080         // 64*65/2 upper-triangle tiles
#define TILES_PER_CTA 15
#define GRID_GEMM 139           // ceil(2080/15)
static constexpr float INV_TEMP = 1.0f / 0.07f;

__device__ __nv_bfloat16 g_nb[NROWS * DIMK];   // normalized bf16 (MMA input)
__device__ float         g_nf[NROWS * DIMK];   // normalized fp32 (pos kernel)
__device__ float         g_rowsum[NROWS];      // diag-excluded exp rowsums (atomic)
__device__ float         g_pos[NROWS];

// ---------------- helpers ----------------
static __device__ __forceinline__ uint32_t smem_u32(const void* p) {
    uint32_t a;
    asm("{ .reg .u64 t; cvta.to.shared.u64 t, %1; cvt.u32.u64 %0, t; }" : "=r"(a) : "l"(p));
    return a;
}
static __device__ __forceinline__ void cp_async16(uint32_t saddr, const void* gptr) {
    asm volatile("cp.async.cg.shared.global [%0], [%1], 16;" :: "r"(saddr), "l"(gptr) : "memory");
}
static __device__ __forceinline__ void cp_commit() {
    asm volatile("cp.async.commit_group;" ::: "memory");
}
template <int N>
static __device__ __forceinline__ void cp_wait() {
    asm volatile("cp.async.wait_group %0;" :: "n"(N) : "memory");
}
static __device__ __forceinline__ void ldsm_x4(uint32_t& r0, uint32_t& r1, uint32_t& r2, uint32_t& r3, uint32_t a) {
    asm volatile("ldmatrix.sync.aligned.m8n8.x4.shared.b16 {%0,%1,%2,%3}, [%4];"
                 : "=r"(r0), "=r"(r1), "=r"(r2), "=r"(r3) : "r"(a));
}
static __device__ __forceinline__ void mma16816(float* c, const uint32_t* a, uint32_t b0, uint32_t b1) {
    asm volatile("mma.sync.aligned.m16n8k16.row.col.f32.bf16.bf16.f32 "
                 "{%0,%1,%2,%3}, {%4,%5,%6,%7}, {%8,%9}, {%0,%1,%2,%3};"
                 : "+f"(c[0]), "+f"(c[1]), "+f"(c[2]), "+f"(c[3])
                 : "r"(a[0]), "r"(a[1]), "r"(a[2]), "r"(a[3]), "r"(b0), "r"(b1));
}

// ---------------- GEMM config ----------------
// Pipeline unit = (tile, k-half): A-half [128x256B] + B-half [128x256B] = 64KB.
static constexpr int HALF_BYTES = 128 * 256;                  // 32768 per operand half
static constexpr int STAGE_BYTES = 2 * HALF_BYTES;            // 65536
static constexpr int SMEM_TOTAL = 2 * STAGE_BYTES;            // 131072 (2 stages)

// Load one K-half of a 128-row tile: rows of 256B, XOR-swizzled 16B units.
static __device__ __forceinline__ void load_half(uint32_t dst, const __nv_bfloat16* __restrict__ src,
                                                 int kh, int tid) {
#pragma unroll
    for (int i = 0; i < 8; i++) {
        int idx = tid + i * 256;            // 2048 16B-units, 16 per row
        int row = idx >> 4, u = idx & 15;
        uint32_t so = dst + (uint32_t)(row << 8) + (uint32_t)((u ^ (row & 7)) << 4);
        cp_async16(so, src + (size_t)row * DIMK + kh * 128 + u * 8);
    }
}

// Map linear triangle index t -> (I <= J) row/col blocks.
static __device__ __forceinline__ void tile_ij(int t, int& I, int& J) {
    int i = 0, base = 0;
    while (base + (NBLK - i) <= t) { base += NBLK - i; i++; }
    I = i; J = i + (t - base);
}

// ---------------- Kernel 1: L2 normalize (+ zero accumulators) ----------------
__global__ void __launch_bounds__(256) normalize_k(const float* __restrict__ emb, float* out) {
    const int gtid = blockIdx.x * 256 + threadIdx.x;
    if (gtid == 0) *out = 0.0f;
    if (gtid < NROWS) g_rowsum[gtid] = 0.0f;
    const int wid = threadIdx.x >> 5, lid = threadIdx.x & 31;
    const int row = blockIdx.x * 8 + wid;
    const float4* src = reinterpret_cast<const float4*>(emb + (size_t)row * DIMK);
    float4 a = src[lid * 2], b = src[lid * 2 + 1];
    float ss = a.x*a.x + a.y*a.y + a.z*a.z + a.w*a.w + b.x*b.x + b.y*b.y + b.z*b.z + b.w*b.w;
#pragma unroll
    for (int o = 16; o > 0; o >>= 1) ss += __shfl_xor_sync(0xffffffffu, ss, o);
    const float inv = 1.0f / fmaxf(sqrtf(ss), 1e-12f);
    a.x *= inv; a.y *= inv; a.z *= inv; a.w *= inv;
    b.x *= inv; b.y *= inv; b.z *= inv; b.w *= inv;
    reinterpret_cast<float4*>(g_nf + (size_t)row * DIMK)[lid * 2]     = a;
    reinterpret_cast<float4*>(g_nf + (size_t)row * DIMK)[lid * 2 + 1] = b;
    uint4 pk;
    pk.x = ((uint32_t)__bfloat16_as_ushort(__float2bfloat16_rn(a.y)) << 16) | (uint32_t)__bfloat16_as_ushort(__float2bfloat16_rn(a.x));
    pk.y = ((uint32_t)__bfloat16_as_ushort(__float2bfloat16_rn(a.w)) << 16) | (uint32_t)__bfloat16_as_ushort(__float2bfloat16_rn(a.z));
    pk.z = ((uint32_t)__bfloat16_as_ushort(__float2bfloat16_rn(b.y)) << 16) | (uint32_t)__bfloat16_as_ushort(__float2bfloat16_rn(b.x));
    pk.w = ((uint32_t)__bfloat16_as_ushort(__float2bfloat16_rn(b.w)) << 16) | (uint32_t)__bfloat16_as_ushort(__float2bfloat16_rn(b.z));
    reinterpret_cast<uint4*>(g_nb + (size_t)row * DIMK)[lid] = pk;
}

// ---------------- Kernel 2: positive sums (exact fp32) ----------------
__global__ void __launch_bounds__(256) pos_k() {
    const int wid = threadIdx.x >> 5, lid = threadIdx.x & 31;
    const int row = blockIdx.x * 8 + wid;
    const float4* xi = reinterpret_cast<const float4*>(g_nf + (size_t)row * DIMK);
    const float4 a = xi[lid * 2], b = xi[lid * 2 + 1];
    const int p = row & (SEQLEN - 1);
    float ps = 1e-8f;
#pragma unroll
    for (int dd = -5; dd <= 5; dd++) {
        if (dd == 0) continue;
        int pj = p + dd;
        if (pj < 0 || pj >= SEQLEN) continue;
        const float4* xj = reinterpret_cast<const float4*>(g_nf + (size_t)(row + dd) * DIMK);
        float4 c = xj[lid * 2], e = xj[lid * 2 + 1];
        float dt = a.x*c.x + a.y*c.y + a.z*c.z + a.w*c.w + b.x*e.x + b.y*e.y + b.z*e.z + b.w*e.w;
#pragma unroll
        for (int o = 16; o > 0; o >>= 1) dt += __shfl_xor_sync(0xffffffffu, dt, o);
        ps += __expf(dt * INV_TEMP);
    }
    if (lid == 0) g_pos[row] = ps;
}

// ---------------- Kernel 3: triangular mma.sync GEMM + fused exp row+col sums ----------------
// 8 warps: wr = wid&3 (M quarter), wc = wid>>2 (N half). Per warp: 2 m16 x 8 n8.
__global__ void __launch_bounds__(256, 1) contrast_gemm() {
    extern __shared__ char smem[];
    const int tid = threadIdx.x, lane = tid & 31, wid = tid >> 5;
    const int wr = wid & 3, wc = wid >> 2;
    const uint32_t sb = smem_u32(smem);
    const int gt0 = blockIdx.x * TILES_PER_CTA;
    const int ntiles = min(TILES_PER_CTA, NTILES_TRI - gt0);

    // Prologue: both K-halves of tile 0
    {
        int I0, J0; tile_ij(gt0, I0, J0);
        load_half(sb,                         g_nb + (size_t)I0 * 128 * DIMK, 0, tid);
        load_half(sb + HALF_BYTES,            g_nb + (size_t)J0 * 128 * DIMK, 0, tid);
        cp_commit();
        load_half(sb + STAGE_BYTES,               g_nb + (size_t)I0 * 128 * DIMK, 1, tid);
        load_half(sb + STAGE_BYTES + HALF_BYTES,  g_nb + (size_t)J0 * 128 * DIMK, 1, tid);
        cp_commit();
    }

    const int lr = lane & 15, hi = lane >> 4;
    const uint32_t rx = (uint32_t)(lr & 7);
    uint32_t a_roff[2], b_roff[4];
#pragma unroll
    for (int mt = 0; mt < 2; mt++) a_roff[mt] = (uint32_t)((wr * 32 + mt * 16 + lr) << 8);
#pragma unroll
    for (int np = 0; np < 4; np++) b_roff[np] = (uint32_t)((wc * 64 + np * 16 + lr) << 8);

    float acc[2][8][4];

    for (int c = 0; c < 2 * ntiles; c++) {
        const int t = c >> 1, kh = c & 1;
        int It, Jt; tile_ij(gt0 + t, It, Jt);

        cp_wait<1>();
        __syncthreads();

        if (kh == 0) {
#pragma unroll
            for (int mt = 0; mt < 2; mt++)
#pragma unroll
                for (int nt = 0; nt < 8; nt++)
#pragma unroll
                    for (int j = 0; j < 4; j++) acc[mt][nt][j] = 0.f;
        }

        const uint32_t stage = sb + (uint32_t)(kh ? STAGE_BYTES : 0);
#pragma unroll
        for (int ks = 0; ks < 8; ks++) {
            const uint32_t koff = ((uint32_t)(2 * ks + hi) ^ rx) << 4;
            uint32_t a[2][4];
            ldsm_x4(a[0][0], a[0][1], a[0][2], a[0][3], stage + a_roff[0] + koff);
            ldsm_x4(a[1][0], a[1][1], a[1][2], a[1][3], stage + a_roff[1] + koff);
#pragma unroll
            for (int np = 0; np < 4; np++) {
                uint32_t b0, b1, b2, b3;
                ldsm_x4(b0, b1, b2, b3, stage + HALF_BYTES + b_roff[np] + koff);
#pragma unroll
                for (int mt = 0; mt < 2; mt++) {
                    mma16816(acc[mt][np * 2 + 0], a[mt], b0, b2);
                    mma16816(acc[mt][np * 2 + 1], a[mt], b1, b3);
                }
            }
        }
        __syncthreads();                    // reads of this stage done

        // Prefetch chunk c+2 = (tile t+1, same kh) into this stage.
        if (t + 1 < ntiles) {
            int I2, J2; tile_ij(gt0 + t + 1, I2, J2);
            if (I2 != It)                   // A-half already resident otherwise
                load_half(stage, g_nb + (size_t)I2 * 128 * DIMK, kh, tid);
            load_half(stage + HALF_BYTES, g_nb + (size_t)J2 * 128 * DIMK, kh, tid);
        }
        cp_commit();                        // one group per iteration (possibly empty)

        if (kh == 1) {
            // Epilogue: exp once; rows of I (rs) and, if off-diag, cols of J (cs).
            const bool diag = (It == Jt);
            const int rowb = It * 128 + wr * 32 + (lane >> 2);
            const int colb = Jt * 128 + wc * 64 + (lane & 3) * 2;
            float rs[4] = {0.f, 0.f, 0.f, 0.f};
            float cs[16];
#pragma unroll
            for (int k = 0; k < 16; k++) cs[k] = 0.f;
#pragma unroll
            for (int mt = 0; mt < 2; mt++)
#pragma unroll
                for (int nt = 0; nt < 8; nt++)
#pragma unroll
                    for (int j = 0; j < 4; j++) {
                        float e = __expf(acc[mt][nt][j] * INV_TEMP);
                        if (diag) {
                            const int col = colb + nt * 8 + (j & 1);
                            const int row = rowb + mt * 16 + (j >> 1) * 8;
                            e = (col != row) ? e : 0.0f;
                        }
                        rs[mt * 2 + (j >> 1)] += e;
                        cs[nt * 2 + (j & 1)] += e;
                    }
#pragma unroll
            for (int q = 0; q < 4; q++) {
                rs[q] += __shfl_xor_sync(0xffffffffu, rs[q], 1);
                rs[q] += __shfl_xor_sync(0xffffffffu, rs[q], 2);
            }
            if ((lane & 3) == 0) {
#pragma unroll
                for (int q = 0; q < 4; q++)
                    atomicAdd(&g_rowsum[It * 128 + wr * 32 + (q >> 1) * 16 + (q & 1) * 8 + (lane >> 2)], rs[q]);
            }
            if (!diag) {
#pragma unroll
                for (int k = 0; k < 16; k++) {
                    cs[k] += __shfl_xor_sync(0xffffffffu, cs[k], 4);
                    cs[k] += __shfl_xor_sync(0xffffffffu, cs[k], 8);
                    cs[k] += __shfl_xor_sync(0xffffffffu, cs[k], 16);
                }
                if (lane < 4) {
#pragma unroll
                    for (int k = 0; k < 16; k++)
                        atomicAdd(&g_rowsum[Jt * 128 + wc * 64 + (k >> 1) * 8 + (lane & 3) * 2 + (k & 1)], cs[k]);
                }
            }
        }
    }
}

// ---------------- Kernel 4: finalize ----------------
__global__ void __launch_bounds__(256) finalize_k(float* out) {
    const int row = blockIdx.x * 256 + threadIdx.x;
    const float all = 1e-8f + g_rowsum[row];
    float l = __logf(g_pos[row] / all);
#pragma unroll
    for (int o = 16; o > 0; o >>= 1) l += __shfl_xor_sync(0xffffffffu, l, o);
    __shared__ float s[8];
    if ((threadIdx.x & 31) == 0) s[threadIdx.x >> 5] = l;
    __syncthreads();
    if (threadIdx.x == 0) {
        float t = 0.0f;
#pragma unroll
        for (int i = 0; i < 8; i++) t += s[i];
        atomicAdd(out, -t * (1.0f / (float)NROWS));
    }
}

extern "C" void kernel_launch(void* const* d_in, const int* in_sizes, int n_in,
                              void* d_out, int out_size) {
    const float* emb = (const float*)d_in[0];
    float* out = (float*)d_out;
    cudaFuncSetAttribute(contrast_gemm, cudaFuncAttributeMaxDynamicSharedMemorySize, SMEM_TOTAL);
    normalize_k<<<NROWS / 8, 256>>>(emb, out);
    pos_k<<<NROWS / 8, 256>>>();
    contrast_gemm<<<GRID_GEMM, 256, SMEM_TOTAL>>>();
    finalize_k<<<NROWS / 256, 256>>>(out);
}

// round 7
// speedup vs baseline: 1.2746x; 1.2349x over previous
#include <cuda_runtime.h>
#include <cuda_bf16.h>
#include <cstdint>

#define NROWS 8192
#define SEQLEN 512
#define DIMK 256
#define NBLK 64                 // 8192 / 128 row-blocks
#define NTILES_TRI 2080         // 64*65/2 upper-triangle tiles
#define TILES_PER_CTA 15
#define GRID_GEMM 139           // ceil(2080/15)
static constexpr float INV_TEMP = 1.0f / 0.07f;

__device__ __nv_bfloat16 g_nb[NROWS * DIMK];   // normalized bf16 (MMA input)
__device__ float         g_nf[NROWS * DIMK];   // normalized fp32 (pos kernel)
__device__ float         g_rowsum[NROWS];      // diag-excluded exp rowsums (atomic)
__device__ float         g_pos[NROWS];

// ---------------- helpers ----------------
static __device__ __forceinline__ uint32_t smem_u32(const void* p) {
    uint32_t a;
    asm("{ .reg .u64 t; cvta.to.shared.u64 t, %1; cvt.u32.u64 %0, t; }" : "=r"(a) : "l"(p));
    return a;
}
static __device__ __forceinline__ void cp_async16(uint32_t saddr, const void* gptr) {
    asm volatile("cp.async.cg.shared.global [%0], [%1], 16;" :: "r"(saddr), "l"(gptr) : "memory");
}
static __device__ __forceinline__ void cp_commit() {
    asm volatile("cp.async.commit_group;" ::: "memory");
}
template <int N>
static __device__ __forceinline__ void cp_wait() {
    asm volatile("cp.async.wait_group %0;" :: "n"(N) : "memory");
}
static __device__ __forceinline__ void ldsm_x4(uint32_t& r0, uint32_t& r1, uint32_t& r2, uint32_t& r3, uint32_t a) {
    asm volatile("ldmatrix.sync.aligned.m8n8.x4.shared.b16 {%0,%1,%2,%3}, [%4];"
                 : "=r"(r0), "=r"(r1), "=r"(r2), "=r"(r3) : "r"(a));
}
static __device__ __forceinline__ void mma16816(float* c, const uint32_t* a, uint32_t b0, uint32_t b1) {
    asm volatile("mma.sync.aligned.m16n8k16.row.col.f32.bf16.bf16.f32 "
                 "{%0,%1,%2,%3}, {%4,%5,%6,%7}, {%8,%9}, {%0,%1,%2,%3};"
                 : "+f"(c[0]), "+f"(c[1]), "+f"(c[2]), "+f"(c[3])
                 : "r"(a[0]), "r"(a[1]), "r"(a[2]), "r"(a[3]), "r"(b0), "r"(b1));
}

// ---------------- GEMM config (R4 pipeline shape) ----------------
static constexpr int TILE_M = 128, TILE_N = 128;
static constexpr int TILE_BYTES = TILE_M * DIMK * 2;           // 65536 (512B per row)
static constexpr int SM_A = 0, SM_B0 = TILE_BYTES, SM_B1 = 2 * TILE_BYTES;
static constexpr int SMEM_TOTAL = 3 * TILE_BYTES;              // 196608

// Async-load one [128 x 512B] tile; 16B units, XOR-swizzled for ldmatrix.
static __device__ __forceinline__ void load_tile_async(uint32_t dst, const __nv_bfloat16* __restrict__ src, int tid) {
#pragma unroll
    for (int i = 0; i < 16; i++) {
        int idx = tid + i * 256;
        int row = idx >> 5, u = idx & 31;
        uint32_t so = dst + (uint32_t)(row << 9) + (uint32_t)(((u ^ (row & 7)) << 4));
        cp_async16(so, src + (size_t)row * DIMK + u * 8);
    }
}

// Map linear triangle index t -> (I <= J) row/col blocks.
static __device__ __forceinline__ void tile_ij(int t, int& I, int& J) {
    int i = 0, base = 0;
    while (base + (NBLK - i) <= t) { base += NBLK - i; i++; }
    I = i; J = i + (t - base);
}

// ---------------- Kernel 1: L2 normalize (+ zero accumulators) ----------------
__global__ void __launch_bounds__(256) normalize_k(const float* __restrict__ emb, float* out) {
    const int gtid = blockIdx.x * 256 + threadIdx.x;
    if (gtid == 0) *out = 0.0f;
    if (gtid < NROWS) g_rowsum[gtid] = 0.0f;
    const int wid = threadIdx.x >> 5, lid = threadIdx.x & 31;
    const int row = blockIdx.x * 8 + wid;
    const float4* src = reinterpret_cast<const float4*>(emb + (size_t)row * DIMK);
    float4 a = src[lid * 2], b = src[lid * 2 + 1];
    float ss = a.x*a.x + a.y*a.y + a.z*a.z + a.w*a.w + b.x*b.x + b.y*b.y + b.z*b.z + b.w*b.w;
#pragma unroll
    for (int o = 16; o > 0; o >>= 1) ss += __shfl_xor_sync(0xffffffffu, ss, o);
    const float inv = 1.0f / fmaxf(sqrtf(ss), 1e-12f);
    a.x *= inv; a.y *= inv; a.z *= inv; a.w *= inv;
    b.x *= inv; b.y *= inv; b.z *= inv; b.w *= inv;
    reinterpret_cast<float4*>(g_nf + (size_t)row * DIMK)[lid * 2]     = a;
    reinterpret_cast<float4*>(g_nf + (size_t)row * DIMK)[lid * 2 + 1] = b;
    uint4 pk;
    pk.x = ((uint32_t)__bfloat16_as_ushort(__float2bfloat16_rn(a.y)) << 16) | (uint32_t)__bfloat16_as_ushort(__float2bfloat16_rn(a.x));
    pk.y = ((uint32_t)__bfloat16_as_ushort(__float2bfloat16_rn(a.w)) << 16) | (uint32_t)__bfloat16_as_ushort(__float2bfloat16_rn(a.z));
    pk.z = ((uint32_t)__bfloat16_as_ushort(__float2bfloat16_rn(b.y)) << 16) | (uint32_t)__bfloat16_as_ushort(__float2bfloat16_rn(b.x));
    pk.w = ((uint32_t)__bfloat16_as_ushort(__float2bfloat16_rn(b.w)) << 16) | (uint32_t)__bfloat16_as_ushort(__float2bfloat16_rn(b.z));
    reinterpret_cast<uint4*>(g_nb + (size_t)row * DIMK)[lid] = pk;
}

// ---------------- Kernel 2: positive sums (exact fp32) ----------------
__global__ void __launch_bounds__(256) pos_k() {
    const int wid = threadIdx.x >> 5, lid = threadIdx.x & 31;
    const int row = blockIdx.x * 8 + wid;
    const float4* xi = reinterpret_cast<const float4*>(g_nf + (size_t)row * DIMK);
    const float4 a = xi[lid * 2], b = xi[lid * 2 + 1];
    const int p = row & (SEQLEN - 1);
    float ps = 1e-8f;
#pragma unroll
    for (int dd = -5; dd <= 5; dd++) {
        if (dd == 0) continue;
        int pj = p + dd;
        if (pj < 0 || pj >= SEQLEN) continue;
        const float4* xj = reinterpret_cast<const float4*>(g_nf + (size_t)(row + dd) * DIMK);
        float4 c = xj[lid * 2], e = xj[lid * 2 + 1];
        float dt = a.x*c.x + a.y*c.y + a.z*c.z + a.w*c.w + b.x*e.x + b.y*e.y + b.z*e.z + b.w*e.w;
#pragma unroll
        for (int o = 16; o > 0; o >>= 1) dt += __shfl_xor_sync(0xffffffffu, dt, o);
        ps += __expf(dt * INV_TEMP);
    }
    if (lid == 0) g_pos[row] = ps;
}

// ---------------- Kernel 3: triangular GEMM, full-K pipeline + fused epilogue ----------------
// 8 warps: wr = wid&3 (M quarter), wc = wid>>2 (N half). Per warp: 2 m16 x 8 n8.
__global__ void __launch_bounds__(256, 1) contrast_gemm() {
    extern __shared__ char smem[];
    const int tid = threadIdx.x, lane = tid & 31, wid = tid >> 5;
    const int wr = wid & 3, wc = wid >> 2;
    const uint32_t sb = smem_u32(smem);
    const int gt0 = blockIdx.x * TILES_PER_CTA;
    const int ntiles = min(TILES_PER_CTA, NTILES_TRI - gt0);

    // Prologue: A(I0) + B(J0) in group 0; B(J1) in group 1.
    int I_res;                               // row-block currently resident in SM_A
    {
        int I0, J0; tile_ij(gt0, I0, J0);
        I_res = I0;
        load_tile_async(sb + SM_A,  g_nb + (size_t)I0 * TILE_M * DIMK, tid);
        load_tile_async(sb + SM_B0, g_nb + (size_t)J0 * TILE_M * DIMK, tid);
        cp_commit();
        if (ntiles > 1) {
            int I1, J1; tile_ij(gt0 + 1, I1, J1);
            load_tile_async(sb + SM_B1, g_nb + (size_t)J1 * TILE_M * DIMK, tid);
        }
        cp_commit();
    }

    const int lr = lane & 15, hi = lane >> 4;
    const uint32_t rx = (uint32_t)(lr & 7);
    uint32_t a_base[2], b_roff[4];
#pragma unroll
    for (int mt = 0; mt < 2; mt++) a_base[mt] = sb + SM_A + (uint32_t)((wr * 32 + mt * 16 + lr) << 9);
#pragma unroll
    for (int np = 0; np < 4; np++) b_roff[np] = (uint32_t)((wc * 64 + np * 16 + lr) << 9);

    for (int t = 0; t < ntiles; t++) {
        int It, Jt; tile_ij(gt0 + t, It, Jt);

        if (It != I_res) {
            // Drain everything, reload A in place, drain again. Rare bubble.
            cp_wait<0>();
            __syncthreads();
            load_tile_async(sb + SM_A, g_nb + (size_t)It * TILE_M * DIMK, tid);
            cp_commit();
            cp_wait<0>();
            __syncthreads();
            I_res = It;
        } else {
            cp_wait<1>();                    // B(t) resident
            __syncthreads();
        }

        const uint32_t bbase = sb + ((t & 1) ? SM_B1 : SM_B0);
        float acc[2][8][4];
#pragma unroll
        for (int mt = 0; mt < 2; mt++)
#pragma unroll
            for (int nt = 0; nt < 8; nt++)
#pragma unroll
                for (int j = 0; j < 4; j++) acc[mt][nt][j] = 0.f;

#pragma unroll 4
        for (int ks = 0; ks < 16; ks++) {
            const uint32_t koff = (uint32_t)(((2 * ks + hi) ^ rx) << 4);
            uint32_t a[2][4];
            ldsm_x4(a[0][0], a[0][1], a[0][2], a[0][3], a_base[0] + koff);
            ldsm_x4(a[1][0], a[1][1], a[1][2], a[1][3], a_base[1] + koff);
#pragma unroll
            for (int np = 0; np < 4; np++) {
                uint32_t b0, b1, b2, b3;
                ldsm_x4(b0, b1, b2, b3, bbase + b_roff[np] + koff);
#pragma unroll
                for (int mt = 0; mt < 2; mt++) {
                    mma16816(acc[mt][np * 2 + 0], a[mt], b0, b2);
                    mma16816(acc[mt][np * 2 + 1], a[mt], b1, b3);
                }
            }
        }
        __syncthreads();                     // all reads of buf[t&1] done

        if (t + 2 < ntiles) {                // prefetch B(t+2) into buf[t&1]
            int I2, J2; tile_ij(gt0 + t + 2, I2, J2);
            load_tile_async(sb + ((t & 1) ? SM_B1 : SM_B0),
                            g_nb + (size_t)J2 * TILE_M * DIMK, tid);
        }
        cp_commit();                         // exactly one group per iteration

        // Fused epilogue: exp once; rows of I (rs); cols of J (cs) if off-diag.
        const bool diag = (It == Jt);
        const int rowb = It * 128 + wr * 32 + (lane >> 2);
        const int colb = Jt * 128 + wc * 64 + (lane & 3) * 2;
        float rs[4] = {0.f, 0.f, 0.f, 0.f};
        float cs[16];
#pragma unroll
        for (int k = 0; k < 16; k++) cs[k] = 0.f;
#pragma unroll
        for (int mt = 0; mt < 2; mt++)
#pragma unroll
            for (int nt = 0; nt < 8; nt++)
#pragma unroll
                for (int j = 0; j < 4; j++) {
                    float e = __expf(acc[mt][nt][j] * INV_TEMP);
                    if (diag) {
                        const int col = colb + nt * 8 + (j & 1);
                        const int row = rowb + mt * 16 + (j >> 1) * 8;
                        e = (col != row) ? e : 0.0f;
                    }
                    rs[mt * 2 + (j >> 1)] += e;
                    cs[nt * 2 + (j & 1)] += e;
                }
#pragma unroll
        for (int q = 0; q < 4; q++) {
            rs[q] += __shfl_xor_sync(0xffffffffu, rs[q], 1);
            rs[q] += __shfl_xor_sync(0xffffffffu, rs[q], 2);
        }
        if ((lane & 3) == 0) {
#pragma unroll
            for (int q = 0; q < 4; q++)
                atomicAdd(&g_rowsum[It * 128 + wr * 32 + (q >> 1) * 16 + (q & 1) * 8 + (lane >> 2)], rs[q]);
        }
        if (!diag) {
#pragma unroll
            for (int k = 0; k < 16; k++) {
                cs[k] += __shfl_xor_sync(0xffffffffu, cs[k], 4);
                cs[k] += __shfl_xor_sync(0xffffffffu, cs[k], 8);
                cs[k] += __shfl_xor_sync(0xffffffffu, cs[k], 16);
            }
            if (lane < 4) {
#pragma unroll
                for (int k = 0; k < 16; k++)
                    atomicAdd(&g_rowsum[Jt * 128 + wc * 64 + (k >> 1) * 8 + (lane & 3) * 2 + (k & 1)], cs[k]);
            }
        }
    }
}

// ---------------- Kernel 4: finalize ----------------
__global__ void __launch_bounds__(256) finalize_k(float* out) {
    const int row = blockIdx.x * 256 + threadIdx.x;
    const float all = 1e-8f + g_rowsum[row];
    float l = __logf(g_pos[row] / all);
#pragma unroll
    for (int o = 16; o > 0; o >>= 1) l += __shfl_xor_sync(0xffffffffu, l, o);
    __shared__ float s[8];
    if ((threadIdx.x & 31) == 0) s[threadIdx.x >> 5] = l;
    __syncthreads();
    if (threadIdx.x == 0) {
        float t = 0.0f;
#pragma unroll
        for (int i = 0; i < 8; i++) t += s[i];
        atomicAdd(out, -t * (1.0f / (float)NROWS));
    }
}

extern "C" void kernel_launch(void* const* d_in, const int* in_sizes, int n_in,
                              void* d_out, int out_size) {
    const float* emb = (const float*)d_in[0];
    float* out = (float*)d_out;
    cudaFuncSetAttribute(contrast_gemm, cudaFuncAttributeMaxDynamicSharedMemorySize, SMEM_TOTAL);
    normalize_k<<<NROWS / 8, 256>>>(emb, out);
    pos_k<<<NROWS / 8, 256>>>();
    contrast_gemm<<<GRID_GEMM, 256, SMEM_TOTAL>>>();
    finalize_k<<<NROWS / 256, 256>>>(out);
}